// round 16
// baseline (speedup 1.0000x reference)
#include <cuda_runtime.h>

// EMA scan via chunked decomposition with decaying look-back (no serial pass).
//   out[l,d,e] = a_e*x[l,d] + (1-a_e)*out[l-1,d,e],  out[-1,d,e] = x[0,d]
//
// CHUNK=32, oS_max = 0.9586^32 = 0.258 -> look-back J=12 terms, trunc <= 9e-8.
//
// Round-16: single knob vs round 15 -- scan __launch_bounds__(256, 7).
//   regs 40 -> <=36 allows 7 blocks/SM: 148*7 = 1036 >= 1024 blocks, so the
//   scan runs in EXACTLY ONE WAVE (at 6/SM it ran 1.15 waves; the tail was
//   ~15% of scan time). Scan main loop needs ~26 live regs, so MLP-8 should
//   survive at 36 (round-5's 32-reg cap did not leave room).
//   aggr: round-14 rescaled single-FMA form, unchanged.

#define LSEQ   8192
#define DFEAT  512
#define EMAS   8
#define CHUNK  32
#define NCHUNK (LSEQ / CHUNK)    // 256
#define DPB    128               // d's per block
#define NDG    (DFEAT / DPB)     // 4
#define TPB    (DPB * 2)         // 256 threads: 2 per d (4 states each)
#define LOOKB  12
#define NST    4                 // states per thread

__device__ float g_B[NCHUNK * DFEAT * EMAS];   // 4 MB scratch

__device__ __forceinline__ void load_coeffs4(const float* __restrict__ log_decay,
                                             int e0, float* a, float* o)
{
    #pragma unroll
    for (int e = 0; e < NST; ++e) {
        float la = log_decay[e0 + e];
        a[e] = 1.0f / (1.0f + expf(-la));
        o[e] = 1.0f - a[e];
    }
}

// ---- Kernel 1: per-chunk aggregates (zero carry-in), rescaled state ----
__global__ __launch_bounds__(TPB, 6)
void ema_aggr(const float* __restrict__ x,
              const float* __restrict__ log_decay)
{
    const int t  = threadIdx.x;
    const int dl = t >> 1;
    const int e0 = (t & 1) * NST;
    const int d  = blockIdx.y * DPB + dl;
    const int k  = blockIdx.x;

    float a[NST], o[NST];
    load_coeffs4(log_decay, e0, a, o);

    float U[NST];                          // B = a * U
    #pragma unroll
    for (int e = 0; e < NST; ++e) U[e] = 0.0f;

    const float* xp = x + (size_t)k * CHUNK * DFEAT + d;

    #pragma unroll
    for (int ii = 0; ii < CHUNK; ii += 8) {
        float xv[8];
        #pragma unroll
        for (int j = 0; j < 8; ++j)           // front-batched, MLP=8
            xv[j] = xp[(size_t)(ii + j) * DFEAT];
        #pragma unroll
        for (int j = 0; j < 8; ++j)
            #pragma unroll
            for (int e = 0; e < NST; ++e)
                U[e] = fmaf(o[e], U[e], xv[j]);   // single FMA per state
    }

    float* bp = g_B + ((size_t)k * DFEAT + d) * EMAS + e0;
    *reinterpret_cast<float4*>(bp) =
        make_float4(a[0] * U[0], a[1] * U[1], a[2] * U[2], a[3] * U[3]);
}

// ---- Kernel 2: look-back carry, then scan + store (round-4 body, 7/SM) ----
__global__ __launch_bounds__(TPB, 7)
void ema_scan(const float* __restrict__ x,
              const float* __restrict__ log_decay,
              float* __restrict__ out)
{
    const int t  = threadIdx.x;
    const int dl = t >> 1;
    const int e0 = (t & 1) * NST;
    const int d  = blockIdx.y * DPB + dl;
    const int k  = blockIdx.x;

    float a[NST], o[NST];
    load_coeffs4(log_decay, e0, a, o);

    // oS = o^CHUNK, CHUNK = 32 = 2^5
    float oS[NST];
    #pragma unroll
    for (int e = 0; e < NST; ++e) {
        float tmp = o[e];
        #pragma unroll
        for (int s = 0; s < 5; ++s) tmp *= tmp;
        oS[e] = tmp;
    }

    // carry(k) = sum_{j=1..min(k,LOOKB)} oS^{j-1} B[k-j]  (+ oS^k * x[0,d] if k<=LOOKB)
    float c[NST], f[NST];
    #pragma unroll
    for (int e = 0; e < NST; ++e) { c[e] = 0.0f; f[e] = 1.0f; }

    #pragma unroll
    for (int j = 1; j <= LOOKB; ++j) {
        if (j <= k) {
            const float* bp = g_B + ((size_t)(k - j) * DFEAT + d) * EMAS + e0;
            const float4 bv = *reinterpret_cast<const float4*>(bp);
            c[0] = fmaf(f[0], bv.x, c[0]);
            c[1] = fmaf(f[1], bv.y, c[1]);
            c[2] = fmaf(f[2], bv.z, c[2]);
            c[3] = fmaf(f[3], bv.w, c[3]);
            #pragma unroll
            for (int e = 0; e < NST; ++e) f[e] *= oS[e];
        }
    }
    if (k <= LOOKB) {                // exact initial-condition term (f = oS^k here)
        const float x0 = x[d];
        #pragma unroll
        for (int e = 0; e < NST; ++e)
            c[e] = fmaf(f[e], x0, c[e]);
    }

    // scan this chunk and store (streaming)
    const float* xp = x + (size_t)k * CHUNK * DFEAT + d;
    float* op = out + ((size_t)k * CHUNK * DFEAT + d) * EMAS + e0;

    #pragma unroll
    for (int ii = 0; ii < CHUNK; ii += 8) {
        float xv[8];
        #pragma unroll
        for (int j = 0; j < 8; ++j)
            xv[j] = xp[(size_t)(ii + j) * DFEAT];
        #pragma unroll
        for (int j = 0; j < 8; ++j) {
            #pragma unroll
            for (int e = 0; e < NST; ++e)
                c[e] = fmaf(o[e], c[e], a[e] * xv[j]);
            __stcs(reinterpret_cast<float4*>(op + (size_t)(ii + j) * (DFEAT * EMAS)),
                   make_float4(c[0], c[1], c[2], c[3]));
        }
    }
}

extern "C" void kernel_launch(void* const* d_in, const int* in_sizes, int n_in,
                              void* d_out, int out_size)
{
    const float* x  = (const float*)d_in[0];
    const float* ld = (const float*)d_in[1];
    if (n_in >= 2 && in_sizes[0] == EMAS && in_sizes[1] == LSEQ * DFEAT) {
        x  = (const float*)d_in[1];
        ld = (const float*)d_in[0];
    }
    float* out = (float*)d_out;

    dim3 grid(NCHUNK, NDG);   // (256, 4) = 1024 blocks, 256 thr each
    ema_aggr<<<grid, TPB>>>(x, ld);
    ema_scan<<<grid, TPB>>>(x, ld, out);
}

// round 17
// speedup vs baseline: 1.0236x; 1.0236x over previous
#include <cuda_runtime.h>

// EMA scan via chunked decomposition with decaying look-back (no serial pass).
//   out[l,d,e] = a_e*x[l,d] + (1-a_e)*out[l-1,d,e],  out[-1,d,e] = x[0,d]
//
// Final config (round-17):
//  * CHUNK=32, look-back J=10: trunc (1-sigmoid(-pi))^(32*10) = 0.258^10
//    ~ 1.3e-6 relative, 3 orders under the 1e-3 tolerance; exact for k<=10.
//  * aggr: rescaled single-FMA form (U' = o*U + x; B = a*U at end), lb(256,6),
//    MLP-8 front-batched loads.  (~3us; 16MB reads)
//  * scan: round-4 body (best measured, 26.7-26.9us): f[]-factor carry loop,
//    MLP-8 x batches, __stcs float4 streaming stores, lb(256,6) -> 40 regs.
//    Scan is pinned at the HBM write wall (128MB @ ~4.8TB/s); reads ride L2.
//
// Structural alternatives measured and rejected: in-block fusion (35.2us),
// PDL (33.5), role-split grid (36.9), stream slicing (43.7), write-back
// stores (45.6), 8 blocks/SM reg-capped (33.5), 7/SM (33.2).

#define LSEQ   8192
#define DFEAT  512
#define EMAS   8
#define CHUNK  32
#define NCHUNK (LSEQ / CHUNK)    // 256
#define DPB    128               // d's per block
#define NDG    (DFEAT / DPB)     // 4
#define TPB    (DPB * 2)         // 256 threads: 2 per d (4 states each)
#define LOOKB  10
#define NST    4                 // states per thread

__device__ float g_B[NCHUNK * DFEAT * EMAS];   // 4 MB scratch

__device__ __forceinline__ void load_coeffs4(const float* __restrict__ log_decay,
                                             int e0, float* a, float* o)
{
    #pragma unroll
    for (int e = 0; e < NST; ++e) {
        float la = log_decay[e0 + e];
        a[e] = 1.0f / (1.0f + expf(-la));
        o[e] = 1.0f - a[e];
    }
}

// ---- Kernel 1: per-chunk aggregates (zero carry-in), rescaled state ----
__global__ __launch_bounds__(TPB, 6)
void ema_aggr(const float* __restrict__ x,
              const float* __restrict__ log_decay)
{
    const int t  = threadIdx.x;
    const int dl = t >> 1;
    const int e0 = (t & 1) * NST;
    const int d  = blockIdx.y * DPB + dl;
    const int k  = blockIdx.x;

    float a[NST], o[NST];
    load_coeffs4(log_decay, e0, a, o);

    float U[NST];                          // B = a * U
    #pragma unroll
    for (int e = 0; e < NST; ++e) U[e] = 0.0f;

    const float* xp = x + (size_t)k * CHUNK * DFEAT + d;

    #pragma unroll
    for (int ii = 0; ii < CHUNK; ii += 8) {
        float xv[8];
        #pragma unroll
        for (int j = 0; j < 8; ++j)           // front-batched, MLP=8
            xv[j] = xp[(size_t)(ii + j) * DFEAT];
        #pragma unroll
        for (int j = 0; j < 8; ++j)
            #pragma unroll
            for (int e = 0; e < NST; ++e)
                U[e] = fmaf(o[e], U[e], xv[j]);   // single FMA per state
    }

    float* bp = g_B + ((size_t)k * DFEAT + d) * EMAS + e0;
    *reinterpret_cast<float4*>(bp) =
        make_float4(a[0] * U[0], a[1] * U[1], a[2] * U[2], a[3] * U[3]);
}

// ---- Kernel 2: look-back carry, then scan + store (round-4 body) ----
__global__ __launch_bounds__(TPB, 6)
void ema_scan(const float* __restrict__ x,
              const float* __restrict__ log_decay,
              float* __restrict__ out)
{
    const int t  = threadIdx.x;
    const int dl = t >> 1;
    const int e0 = (t & 1) * NST;
    const int d  = blockIdx.y * DPB + dl;
    const int k  = blockIdx.x;

    float a[NST], o[NST];
    load_coeffs4(log_decay, e0, a, o);

    // oS = o^CHUNK, CHUNK = 32 = 2^5
    float oS[NST];
    #pragma unroll
    for (int e = 0; e < NST; ++e) {
        float tmp = o[e];
        #pragma unroll
        for (int s = 0; s < 5; ++s) tmp *= tmp;
        oS[e] = tmp;
    }

    // carry(k) = sum_{j=1..min(k,LOOKB)} oS^{j-1} B[k-j]  (+ oS^k * x[0,d] if k<=LOOKB)
    float c[NST], f[NST];
    #pragma unroll
    for (int e = 0; e < NST; ++e) { c[e] = 0.0f; f[e] = 1.0f; }

    #pragma unroll
    for (int j = 1; j <= LOOKB; ++j) {
        if (j <= k) {
            const float* bp = g_B + ((size_t)(k - j) * DFEAT + d) * EMAS + e0;
            const float4 bv = *reinterpret_cast<const float4*>(bp);
            c[0] = fmaf(f[0], bv.x, c[0]);
            c[1] = fmaf(f[1], bv.y, c[1]);
            c[2] = fmaf(f[2], bv.z, c[2]);
            c[3] = fmaf(f[3], bv.w, c[3]);
            #pragma unroll
            for (int e = 0; e < NST; ++e) f[e] *= oS[e];
        }
    }
    if (k <= LOOKB) {                // exact initial-condition term (f = oS^k here)
        const float x0 = x[d];
        #pragma unroll
        for (int e = 0; e < NST; ++e)
            c[e] = fmaf(f[e], x0, c[e]);
    }

    // scan this chunk and store (streaming)
    const float* xp = x + (size_t)k * CHUNK * DFEAT + d;
    float* op = out + ((size_t)k * CHUNK * DFEAT + d) * EMAS + e0;

    #pragma unroll
    for (int ii = 0; ii < CHUNK; ii += 8) {
        float xv[8];
        #pragma unroll
        for (int j = 0; j < 8; ++j)
            xv[j] = xp[(size_t)(ii + j) * DFEAT];
        #pragma unroll
        for (int j = 0; j < 8; ++j) {
            #pragma unroll
            for (int e = 0; e < NST; ++e)
                c[e] = fmaf(o[e], c[e], a[e] * xv[j]);
            __stcs(reinterpret_cast<float4*>(op + (size_t)(ii + j) * (DFEAT * EMAS)),
                   make_float4(c[0], c[1], c[2], c[3]));
        }
    }
}

extern "C" void kernel_launch(void* const* d_in, const int* in_sizes, int n_in,
                              void* d_out, int out_size)
{
    const float* x  = (const float*)d_in[0];
    const float* ld = (const float*)d_in[1];
    if (n_in >= 2 && in_sizes[0] == EMAS && in_sizes[1] == LSEQ * DFEAT) {
        x  = (const float*)d_in[1];
        ld = (const float*)d_in[0];
    }
    float* out = (float*)d_out;

    dim3 grid(NCHUNK, NDG);   // (256, 4) = 1024 blocks, 256 thr each
    ema_aggr<<<grid, TPB>>>(x, ld);
    ema_scan<<<grid, TPB>>>(x, ld, out);
}